// round 9
// baseline (speedup 1.0000x reference)
#include <cuda_runtime.h>
#include <cuda_bf16.h>
#include <cstdint>

#define N_NODES 50000
#define N_EDGES 800000
#define XD 128
#define HD 256
#define YD 128

// Scratch buffers (static device allocations; legal per harness rules)
__device__ float g_t  [(size_t)N_NODES * YD];  // t = h @ W2
__device__ float g_ax [(size_t)N_NODES * XD];  // A @ xn
__device__ float g_h  [(size_t)N_NODES * HD];  // relu(ax @ W1 + b1)
__device__ float g_inv[N_NODES];               // 1/(rowsum(x)+1e-4)

// CSR scratch (rebuilt every launch — deterministic work)
__device__ int  g_cnt   [N_NODES];
__device__ int  g_rowptr[N_NODES + 1];
__device__ int  g_cursor[N_NODES];
__device__ int2 g_edge  [N_EDGES];             // .x = col, .y = val bits

// ---------------------------------------------------------------------------
// CSR build
// ---------------------------------------------------------------------------
__global__ __launch_bounds__(256) void csr_hist_kernel(const int* __restrict__ rows) {
    int e = blockIdx.x * blockDim.x + threadIdx.x;
    if (e < N_EDGES) atomicAdd(&g_cnt[rows[e]], 1);
}

// Two-level shfl scan over 1024 chunk-sums (CHUNK=49 rows each).
__global__ __launch_bounds__(1024) void csr_scan_kernel() {
    __shared__ int warp_tot[32];
    const int t    = threadIdx.x;
    const int lane = t & 31;
    const int wid  = t >> 5;
    const int CHUNK = (N_NODES + 1023) / 1024;   // 49
    const int base = t * CHUNK;

    int local = 0;
    #pragma unroll 7
    for (int i = 0; i < CHUNK; i++) {
        int idx = base + i;
        if (idx < N_NODES) local += g_cnt[idx];
    }
    // inclusive warp scan
    int v = local;
    #pragma unroll
    for (int o = 1; o < 32; o <<= 1) {
        int u = __shfl_up_sync(0xFFFFFFFFu, v, o);
        if (lane >= o) v += u;
    }
    if (lane == 31) warp_tot[wid] = v;
    __syncthreads();
    if (wid == 0) {
        int w = warp_tot[lane];
        #pragma unroll
        for (int o = 1; o < 32; o <<= 1) {
            int u = __shfl_up_sync(0xFFFFFFFFu, w, o);
            if (lane >= o) w += u;
        }
        warp_tot[lane] = w;
    }
    __syncthreads();
    int incl = v + (wid > 0 ? warp_tot[wid - 1] : 0);   // inclusive over all threads
    int pre = incl - local;                              // exclusive prefix
    #pragma unroll 7
    for (int i = 0; i < CHUNK; i++) {
        int idx = base + i;
        if (idx < N_NODES) {
            g_rowptr[idx] = pre;
            g_cursor[idx] = pre;
            pre += g_cnt[idx];
        }
    }
    if (t == 1023) g_rowptr[N_NODES] = incl;
}

__global__ __launch_bounds__(256) void csr_scatter_kernel(
    const float* __restrict__ vals,
    const int*   __restrict__ rows,
    const int*   __restrict__ cols)
{
    int e = blockIdx.x * blockDim.x + threadIdx.x;
    if (e >= N_EDGES) return;
    int r = rows[e];
    int c = cols[e];
    float v = vals[e];
    int pos = atomicAdd(&g_cursor[r], 1);
    g_edge[pos] = make_int2(c, __float_as_int(v));
}

// ---------------------------------------------------------------------------
// Row sums -> g_inv[i] = 1/(sum_j x[i,j] + 1e-4). One warp per row.
// ---------------------------------------------------------------------------
__global__ __launch_bounds__(256) void rowsum_kernel(const float* __restrict__ x) {
    int row  = (blockIdx.x * blockDim.x + threadIdx.x) >> 5;
    int lane = threadIdx.x & 31;
    if (row >= N_NODES) return;
    float4 v = reinterpret_cast<const float4*>(x + (size_t)row * XD)[lane];
    float s = v.x + v.y + v.z + v.w;
    #pragma unroll
    for (int o = 16; o > 0; o >>= 1) s += __shfl_xor_sync(0xFFFFFFFFu, s, o);
    if (lane == 0) g_inv[row] = 1.0f / (s + 1e-4f);
}

// ---------------------------------------------------------------------------
// CSR SpMM, D=128: one warp per output row, float4 accumulators in registers.
// SCALE_SRC folds the row-normalization of the gathered source in on the fly:
//   dst[row,:] = (bias?) + sum_e val_e * (inv[col_e]?) * src[col_e,:]
// ---------------------------------------------------------------------------
template<bool HAS_BIAS, bool SCALE_SRC>
__global__ __launch_bounds__(256) void spmm_csr128_kernel(
    const float* __restrict__ src,
    const float* __restrict__ bias,
    float*       __restrict__ dst)
{
    int row  = (blockIdx.x * blockDim.x + threadIdx.x) >> 5;
    int lane = threadIdx.x & 31;
    if (row >= N_NODES) return;

    int s = g_rowptr[row];
    int e = g_rowptr[row + 1];

    float4 acc;
    if (HAS_BIAS) acc = reinterpret_cast<const float4*>(bias)[lane];
    else          acc = make_float4(0.f, 0.f, 0.f, 0.f);

    const float4* src4 = reinterpret_cast<const float4*>(src);

    int i = s;
    for (; i + 4 <= e; i += 4) {
        int2 e0 = __ldg(&g_edge[i]);
        int2 e1 = __ldg(&g_edge[i + 1]);
        int2 e2 = __ldg(&g_edge[i + 2]);
        int2 e3 = __ldg(&g_edge[i + 3]);
        float v0 = __int_as_float(e0.y);
        float v1 = __int_as_float(e1.y);
        float v2 = __int_as_float(e2.y);
        float v3 = __int_as_float(e3.y);
        if (SCALE_SRC) {
            v0 *= __ldg(&g_inv[e0.x]);
            v1 *= __ldg(&g_inv[e1.x]);
            v2 *= __ldg(&g_inv[e2.x]);
            v3 *= __ldg(&g_inv[e3.x]);
        }
        float4 m0 = __ldg(&src4[(size_t)e0.x * 32 + lane]);
        float4 m1 = __ldg(&src4[(size_t)e1.x * 32 + lane]);
        float4 m2 = __ldg(&src4[(size_t)e2.x * 32 + lane]);
        float4 m3 = __ldg(&src4[(size_t)e3.x * 32 + lane]);
        acc.x = fmaf(v0, m0.x, acc.x); acc.y = fmaf(v0, m0.y, acc.y);
        acc.z = fmaf(v0, m0.z, acc.z); acc.w = fmaf(v0, m0.w, acc.w);
        acc.x = fmaf(v1, m1.x, acc.x); acc.y = fmaf(v1, m1.y, acc.y);
        acc.z = fmaf(v1, m1.z, acc.z); acc.w = fmaf(v1, m1.w, acc.w);
        acc.x = fmaf(v2, m2.x, acc.x); acc.y = fmaf(v2, m2.y, acc.y);
        acc.z = fmaf(v2, m2.z, acc.z); acc.w = fmaf(v2, m2.w, acc.w);
        acc.x = fmaf(v3, m3.x, acc.x); acc.y = fmaf(v3, m3.y, acc.y);
        acc.z = fmaf(v3, m3.z, acc.z); acc.w = fmaf(v3, m3.w, acc.w);
    }
    for (; i < e; i++) {
        int2 e0 = __ldg(&g_edge[i]);
        float v0 = __int_as_float(e0.y);
        if (SCALE_SRC) v0 *= __ldg(&g_inv[e0.x]);
        float4 m0 = __ldg(&src4[(size_t)e0.x * 32 + lane]);
        acc.x = fmaf(v0, m0.x, acc.x); acc.y = fmaf(v0, m0.y, acc.y);
        acc.z = fmaf(v0, m0.z, acc.z); acc.w = fmaf(v0, m0.w, acc.w);
    }
    reinterpret_cast<float4*>(dst)[(size_t)row * 32 + lane] = acc;
}

// ---------------------------------------------------------------------------
// TF32 tensor-core GEMM: out[M,N] = op(A[M,K] @ W[K,N] + bias)
// Block tile 128x128, BK=32, 8 warps (4 along M x 2 along N), warp tile 32x64.
// ---------------------------------------------------------------------------
__device__ __forceinline__ uint32_t f2tf32(float f) {
    uint32_t r;
    asm("cvt.rna.tf32.f32 %0, %1;" : "=r"(r) : "f"(f));
    return r;
}
__device__ __forceinline__ void mma_tf32(float* d, const uint32_t* a, const uint32_t* b) {
    asm volatile("mma.sync.aligned.m16n8k8.row.col.f32.tf32.tf32.f32 "
                 "{%0,%1,%2,%3}, {%4,%5,%6,%7}, {%8,%9}, {%0,%1,%2,%3};"
                 : "+f"(d[0]), "+f"(d[1]), "+f"(d[2]), "+f"(d[3])
                 : "r"(a[0]), "r"(a[1]), "r"(a[2]), "r"(a[3]),
                   "r"(b[0]), "r"(b[1]));
}

template<int N_DIM, int K_DIM, bool RELU, bool HAS_BIAS>
__global__ __launch_bounds__(256) void gemm_tf32_kernel(
    const float* __restrict__ A,
    const float* __restrict__ W,
    const float* __restrict__ bias,
    float*       __restrict__ out,
    int M)
{
    constexpr int BM = 128, BN = 128, BK = 32;
    constexpr int LDA = BK + 4;   // 36
    constexpr int LDW = BN + 4;   // 132
    __shared__ uint32_t As[BM * LDA];
    __shared__ uint32_t Ws[BK * LDW];

    const int tid  = threadIdx.x;
    const int lane = tid & 31;
    const int wid  = tid >> 5;
    const int g    = lane >> 2;
    const int tg   = lane & 3;
    const int warp_m = (wid & 3) * 32;
    const int warp_n = (wid >> 2) * 64;
    const int row0 = blockIdx.x * BM;
    const int col0 = blockIdx.y * BN;

    float acc[2][8][4];
    #pragma unroll
    for (int mt = 0; mt < 2; mt++)
        #pragma unroll
        for (int nt = 0; nt < 8; nt++)
            #pragma unroll
            for (int j = 0; j < 4; j++) acc[mt][nt][j] = 0.f;

    for (int k0 = 0; k0 < K_DIM; k0 += BK) {
        #pragma unroll
        for (int i = 0; i < 4; i++) {
            int idx = tid + 256 * i;
            int r   = idx >> 3;
            int kc  = (idx & 7) * 4;
            int gr  = row0 + r; if (gr >= M) gr = M - 1;
            float4 v = *reinterpret_cast<const float4*>(A + (size_t)gr * K_DIM + k0 + kc);
            uint4 u = make_uint4(f2tf32(v.x), f2tf32(v.y), f2tf32(v.z), f2tf32(v.w));
            *reinterpret_cast<uint4*>(&As[r * LDA + kc]) = u;
        }
        #pragma unroll
        for (int i = 0; i < 4; i++) {
            int idx = tid + 256 * i;
            int kk  = idx >> 5;
            int c   = (idx & 31) * 4;
            float4 v = *reinterpret_cast<const float4*>(W + (size_t)(k0 + kk) * N_DIM + col0 + c);
            uint4 u = make_uint4(f2tf32(v.x), f2tf32(v.y), f2tf32(v.z), f2tf32(v.w));
            *reinterpret_cast<uint4*>(&Ws[kk * LDW + c]) = u;
        }
        __syncthreads();

        #pragma unroll
        for (int ks = 0; ks < BK; ks += 8) {
            uint32_t afr[2][4];
            #pragma unroll
            for (int mt = 0; mt < 2; mt++) {
                int r = warp_m + mt * 16 + g;
                afr[mt][0] = As[(r    ) * LDA + ks + tg];
                afr[mt][1] = As[(r + 8) * LDA + ks + tg];
                afr[mt][2] = As[(r    ) * LDA + ks + tg + 4];
                afr[mt][3] = As[(r + 8) * LDA + ks + tg + 4];
            }
            uint32_t bfr[8][2];
            #pragma unroll
            for (int nt = 0; nt < 8; nt++) {
                int c = warp_n + nt * 8 + g;
                bfr[nt][0] = Ws[(ks + tg    ) * LDW + c];
                bfr[nt][1] = Ws[(ks + tg + 4) * LDW + c];
            }
            #pragma unroll
            for (int mt = 0; mt < 2; mt++)
                #pragma unroll
                for (int nt = 0; nt < 8; nt++)
                    mma_tf32(acc[mt][nt], afr[mt], bfr[nt]);
        }
        __syncthreads();
    }

    float2 bv[8];
    #pragma unroll
    for (int nt = 0; nt < 8; nt++) {
        if (HAS_BIAS) {
            int c = col0 + warp_n + nt * 8 + tg * 2;
            bv[nt] = *reinterpret_cast<const float2*>(bias + c);
        } else {
            bv[nt] = make_float2(0.f, 0.f);
        }
    }
    #pragma unroll
    for (int mt = 0; mt < 2; mt++) {
        #pragma unroll
        for (int half = 0; half < 2; half++) {
            int m = row0 + warp_m + mt * 16 + half * 8 + g;
            if (m < M) {
                #pragma unroll
                for (int nt = 0; nt < 8; nt++) {
                    int c = col0 + warp_n + nt * 8 + tg * 2;
                    float vx = acc[mt][nt][half * 2 + 0] + bv[nt].x;
                    float vy = acc[mt][nt][half * 2 + 1] + bv[nt].y;
                    if (RELU) { vx = fmaxf(vx, 0.f); vy = fmaxf(vy, 0.f); }
                    *reinterpret_cast<float2*>(out + (size_t)m * N_DIM + c) =
                        make_float2(vx, vy);
                }
            }
        }
    }
}

// ---------------------------------------------------------------------------
extern "C" void kernel_launch(void* const* d_in, const int* in_sizes, int n_in,
                              void* d_out, int out_size) {
    const float* x        = (const float*)d_in[0];
    const float* adj_vals = (const float*)d_in[1];
    const int*   adj_row  = (const int*)  d_in[2];
    const int*   adj_col  = (const int*)  d_in[3];
    const float* W1       = (const float*)d_in[4];
    const float* b1       = (const float*)d_in[5];
    const float* W2       = (const float*)d_in[6];
    const float* b2       = (const float*)d_in[7];
    float* y = (float*)d_out;

    float *t, *ax, *h;
    int* cnt;
    cudaGetSymbolAddress((void**)&t,   g_t);
    cudaGetSymbolAddress((void**)&ax,  g_ax);
    cudaGetSymbolAddress((void**)&h,   g_h);
    cudaGetSymbolAddress((void**)&cnt, g_cnt);

    // --- CSR build (shared by both SpMMs) ---
    cudaMemsetAsync(cnt, 0, N_NODES * sizeof(int));
    csr_hist_kernel<<<(N_EDGES + 255) / 256, 256>>>(adj_row);
    csr_scan_kernel<<<1, 1024>>>();
    csr_scatter_kernel<<<(N_EDGES + 255) / 256, 256>>>(adj_vals, adj_row, adj_col);

    // --- row sums -> g_inv ---
    rowsum_kernel<<<(N_NODES * 32 + 255) / 256, 256>>>(x);

    // --- spmm1: g_ax = A @ (x row-normalized on the fly) ---
    spmm_csr128_kernel<false, true><<<(N_NODES * 32 + 255) / 256, 256>>>(x, nullptr, ax);

    // --- gemm1: g_h = relu(g_ax @ W1 + b1)  [50000x256], K=128 ---
    {
        dim3 grid((N_NODES + 127) / 128, HD / 128);
        gemm_tf32_kernel<HD, XD, true, true><<<grid, 256>>>(ax, W1, b1, h, N_NODES);
    }
    // --- gemm2: t = g_h @ W2  [50000x128], K=256 (bias folded into spmm2) ---
    {
        dim3 grid((N_NODES + 127) / 128, YD / 128);
        gemm_tf32_kernel<YD, HD, false, false><<<grid, 256>>>(h, W2, nullptr, t, N_NODES);
    }
    // --- spmm2: y = b2 + A @ t ---
    spmm_csr128_kernel<true, false><<<(N_NODES * 32 + 255) / 256, 256>>>(t, b2, y);
}

// round 10
// speedup vs baseline: 1.0277x; 1.0277x over previous
#include <cuda_runtime.h>
#include <cuda_bf16.h>
#include <cstdint>

#define N_NODES 50000
#define N_EDGES 800000
#define XD 128
#define HD 256
#define YD 128

// Scratch buffers (static device allocations; legal per harness rules)
__device__ __nv_bfloat16 g_xb[(size_t)N_NODES * XD];  // bf16 copy of x
__device__ __nv_bfloat16 g_tb[(size_t)N_NODES * YD];  // bf16 t = h @ W2
__device__ float g_ax [(size_t)N_NODES * XD];          // A @ xn (fp32)
__device__ float g_h  [(size_t)N_NODES * HD];          // relu(ax @ W1 + b1)
__device__ float g_inv[N_NODES];                       // 1/(rowsum(x)+1e-4)

// CSR scratch (rebuilt every launch — deterministic work)
__device__ int  g_cnt   [N_NODES];
__device__ int  g_rowptr[N_NODES + 1];
__device__ int  g_cursor[N_NODES];
__device__ int2 g_edge  [N_EDGES];             // .x = col, .y = val bits

// ---------------------------------------------------------------------------
// CSR build
// ---------------------------------------------------------------------------
__global__ __launch_bounds__(256) void csr_hist_kernel(const int* __restrict__ rows) {
    int e = blockIdx.x * blockDim.x + threadIdx.x;
    if (e < N_EDGES) atomicAdd(&g_cnt[rows[e]], 1);
}

// Two-level shfl scan over 1024 chunk-sums (CHUNK=49 rows each).
__global__ __launch_bounds__(1024) void csr_scan_kernel() {
    __shared__ int warp_tot[32];
    const int t    = threadIdx.x;
    const int lane = t & 31;
    const int wid  = t >> 5;
    const int CHUNK = (N_NODES + 1023) / 1024;   // 49
    const int base = t * CHUNK;

    int local = 0;
    #pragma unroll 7
    for (int i = 0; i < CHUNK; i++) {
        int idx = base + i;
        if (idx < N_NODES) local += g_cnt[idx];
    }
    int v = local;
    #pragma unroll
    for (int o = 1; o < 32; o <<= 1) {
        int u = __shfl_up_sync(0xFFFFFFFFu, v, o);
        if (lane >= o) v += u;
    }
    if (lane == 31) warp_tot[wid] = v;
    __syncthreads();
    if (wid == 0) {
        int w = warp_tot[lane];
        #pragma unroll
        for (int o = 1; o < 32; o <<= 1) {
            int u = __shfl_up_sync(0xFFFFFFFFu, w, o);
            if (lane >= o) w += u;
        }
        warp_tot[lane] = w;
    }
    __syncthreads();
    int incl = v + (wid > 0 ? warp_tot[wid - 1] : 0);
    int pre = incl - local;
    #pragma unroll 7
    for (int i = 0; i < CHUNK; i++) {
        int idx = base + i;
        if (idx < N_NODES) {
            g_rowptr[idx] = pre;
            g_cursor[idx] = pre;
            pre += g_cnt[idx];
        }
    }
    if (t == 1023) g_rowptr[N_NODES] = incl;
}

__global__ __launch_bounds__(256) void csr_scatter_kernel(
    const float* __restrict__ vals,
    const int*   __restrict__ rows,
    const int*   __restrict__ cols)
{
    int e = blockIdx.x * blockDim.x + threadIdx.x;
    if (e >= N_EDGES) return;
    int r = rows[e];
    int c = cols[e];
    float v = vals[e];
    int pos = atomicAdd(&g_cursor[r], 1);
    g_edge[pos] = make_int2(c, __float_as_int(v));
}

// ---------------------------------------------------------------------------
// Fused row-sum + bf16 convert: g_inv[i] = 1/(sum_j x[i,j]+1e-4); g_xb = bf16(x).
// One warp per row.
// ---------------------------------------------------------------------------
__global__ __launch_bounds__(256) void rowsum_cvt_kernel(const float* __restrict__ x) {
    int row  = (blockIdx.x * blockDim.x + threadIdx.x) >> 5;
    int lane = threadIdx.x & 31;
    if (row >= N_NODES) return;
    float4 v = reinterpret_cast<const float4*>(x + (size_t)row * XD)[lane];
    float s = v.x + v.y + v.z + v.w;
    #pragma unroll
    for (int o = 16; o > 0; o >>= 1) s += __shfl_xor_sync(0xFFFFFFFFu, s, o);
    if (lane == 0) g_inv[row] = 1.0f / (s + 1e-4f);
    // bf16 pack: 4 values -> uint2
    __nv_bfloat162 p0 = __floats2bfloat162_rn(v.x, v.y);
    __nv_bfloat162 p1 = __floats2bfloat162_rn(v.z, v.w);
    uint2 u = make_uint2(*reinterpret_cast<uint32_t*>(&p0),
                         *reinterpret_cast<uint32_t*>(&p1));
    reinterpret_cast<uint2*>(g_xb)[(size_t)row * 32 + lane] = u;
}

// ---------------------------------------------------------------------------
// CSR SpMM with bf16 source, D=128: one warp per row, 4 fp32 acc per lane.
// Gather is 256B/row (bf16) instead of 512B — L2-BW-bound, so ~2x faster.
//   dst[row,:] = (bias?) + sum_e val_e * (inv[col_e]?) * bf16src[col_e,:]
// ---------------------------------------------------------------------------
template<bool HAS_BIAS, bool SCALE_SRC>
__global__ __launch_bounds__(256) void spmm_bf16_kernel(
    const __nv_bfloat16* __restrict__ src,
    const float*         __restrict__ bias,
    float*               __restrict__ dst)
{
    int row  = (blockIdx.x * blockDim.x + threadIdx.x) >> 5;
    int lane = threadIdx.x & 31;
    if (row >= N_NODES) return;

    int s = g_rowptr[row];
    int e = g_rowptr[row + 1];

    float4 acc;
    if (HAS_BIAS) acc = reinterpret_cast<const float4*>(bias)[lane];
    else          acc = make_float4(0.f, 0.f, 0.f, 0.f);

    const uint2* src2 = reinterpret_cast<const uint2*>(src);  // row stride: 32 uint2

    #pragma unroll 1
    for (int i = s; i + 4 <= e; i += 4) {
        int2 e0 = __ldg(&g_edge[i]);
        int2 e1 = __ldg(&g_edge[i + 1]);
        int2 e2 = __ldg(&g_edge[i + 2]);
        int2 e3 = __ldg(&g_edge[i + 3]);
        float v0 = __int_as_float(e0.y);
        float v1 = __int_as_float(e1.y);
        float v2 = __int_as_float(e2.y);
        float v3 = __int_as_float(e3.y);
        if (SCALE_SRC) {
            v0 *= __ldg(&g_inv[e0.x]);
            v1 *= __ldg(&g_inv[e1.x]);
            v2 *= __ldg(&g_inv[e2.x]);
            v3 *= __ldg(&g_inv[e3.x]);
        }
        uint2 m0 = __ldg(&src2[(size_t)e0.x * 32 + lane]);
        uint2 m1 = __ldg(&src2[(size_t)e1.x * 32 + lane]);
        uint2 m2 = __ldg(&src2[(size_t)e2.x * 32 + lane]);
        uint2 m3 = __ldg(&src2[(size_t)e3.x * 32 + lane]);
        float2 f0a = __bfloat1622float2(*reinterpret_cast<__nv_bfloat162*>(&m0.x));
        float2 f0b = __bfloat1622float2(*reinterpret_cast<__nv_bfloat162*>(&m0.y));
        float2 f1a = __bfloat1622float2(*reinterpret_cast<__nv_bfloat162*>(&m1.x));
        float2 f1b = __bfloat1622float2(*reinterpret_cast<__nv_bfloat162*>(&m1.y));
        float2 f2a = __bfloat1622float2(*reinterpret_cast<__nv_bfloat162*>(&m2.x));
        float2 f2b = __bfloat1622float2(*reinterpret_cast<__nv_bfloat162*>(&m2.y));
        float2 f3a = __bfloat1622float2(*reinterpret_cast<__nv_bfloat162*>(&m3.x));
        float2 f3b = __bfloat1622float2(*reinterpret_cast<__nv_bfloat162*>(&m3.y));
        acc.x = fmaf(v0, f0a.x, acc.x); acc.y = fmaf(v0, f0a.y, acc.y);
        acc.z = fmaf(v0, f0b.x, acc.z); acc.w = fmaf(v0, f0b.y, acc.w);
        acc.x = fmaf(v1, f1a.x, acc.x); acc.y = fmaf(v1, f1a.y, acc.y);
        acc.z = fmaf(v1, f1b.x, acc.z); acc.w = fmaf(v1, f1b.y, acc.w);
        acc.x = fmaf(v2, f2a.x, acc.x); acc.y = fmaf(v2, f2a.y, acc.y);
        acc.z = fmaf(v2, f2b.x, acc.z); acc.w = fmaf(v2, f2b.y, acc.w);
        acc.x = fmaf(v3, f3a.x, acc.x); acc.y = fmaf(v3, f3a.y, acc.y);
        acc.z = fmaf(v3, f3b.x, acc.z); acc.w = fmaf(v3, f3b.y, acc.w);
    }
    int rem = s + ((e - s) & ~3);
    for (int i = rem; i < e; i++) {
        int2 e0 = __ldg(&g_edge[i]);
        float v0 = __int_as_float(e0.y);
        if (SCALE_SRC) v0 *= __ldg(&g_inv[e0.x]);
        uint2 m0 = __ldg(&src2[(size_t)e0.x * 32 + lane]);
        float2 f0a = __bfloat1622float2(*reinterpret_cast<__nv_bfloat162*>(&m0.x));
        float2 f0b = __bfloat1622float2(*reinterpret_cast<__nv_bfloat162*>(&m0.y));
        acc.x = fmaf(v0, f0a.x, acc.x); acc.y = fmaf(v0, f0a.y, acc.y);
        acc.z = fmaf(v0, f0b.x, acc.z); acc.w = fmaf(v0, f0b.y, acc.w);
    }
    reinterpret_cast<float4*>(dst)[(size_t)row * 32 + lane] = acc;
}

// ---------------------------------------------------------------------------
// TF32 tensor-core GEMM: out[M,N] = op(A[M,K] @ W[K,N] + bias)
// Block tile 128x128, BK=32, 8 warps, warp tile 32x64. OUT_BF16 stores bf16.
// ---------------------------------------------------------------------------
__device__ __forceinline__ uint32_t f2tf32(float f) {
    uint32_t r;
    asm("cvt.rna.tf32.f32 %0, %1;" : "=r"(r) : "f"(f));
    return r;
}
__device__ __forceinline__ void mma_tf32(float* d, const uint32_t* a, const uint32_t* b) {
    asm volatile("mma.sync.aligned.m16n8k8.row.col.f32.tf32.tf32.f32 "
                 "{%0,%1,%2,%3}, {%4,%5,%6,%7}, {%8,%9}, {%0,%1,%2,%3};"
                 : "+f"(d[0]), "+f"(d[1]), "+f"(d[2]), "+f"(d[3])
                 : "r"(a[0]), "r"(a[1]), "r"(a[2]), "r"(a[3]),
                   "r"(b[0]), "r"(b[1]));
}

template<int N_DIM, int K_DIM, bool RELU, bool HAS_BIAS, bool OUT_BF16>
__global__ __launch_bounds__(256) void gemm_tf32_kernel(
    const float* __restrict__ A,
    const float* __restrict__ W,
    const float* __restrict__ bias,
    void*        __restrict__ out,
    int M)
{
    constexpr int BM = 128, BN = 128, BK = 32;
    constexpr int LDA = BK + 4;   // 36
    constexpr int LDW = BN + 4;   // 132
    __shared__ uint32_t As[BM * LDA];
    __shared__ uint32_t Ws[BK * LDW];

    const int tid  = threadIdx.x;
    const int lane = tid & 31;
    const int wid  = tid >> 5;
    const int g    = lane >> 2;
    const int tg   = lane & 3;
    const int warp_m = (wid & 3) * 32;
    const int warp_n = (wid >> 2) * 64;
    const int row0 = blockIdx.x * BM;
    const int col0 = blockIdx.y * BN;

    float acc[2][8][4];
    #pragma unroll
    for (int mt = 0; mt < 2; mt++)
        #pragma unroll
        for (int nt = 0; nt < 8; nt++)
            #pragma unroll
            for (int j = 0; j < 4; j++) acc[mt][nt][j] = 0.f;

    for (int k0 = 0; k0 < K_DIM; k0 += BK) {
        #pragma unroll
        for (int i = 0; i < 4; i++) {
            int idx = tid + 256 * i;
            int r   = idx >> 3;
            int kc  = (idx & 7) * 4;
            int gr  = row0 + r; if (gr >= M) gr = M - 1;
            float4 v = *reinterpret_cast<const float4*>(A + (size_t)gr * K_DIM + k0 + kc);
            uint4 u = make_uint4(f2tf32(v.x), f2tf32(v.y), f2tf32(v.z), f2tf32(v.w));
            *reinterpret_cast<uint4*>(&As[r * LDA + kc]) = u;
        }
        #pragma unroll
        for (int i = 0; i < 4; i++) {
            int idx = tid + 256 * i;
            int kk  = idx >> 5;
            int c   = (idx & 31) * 4;
            float4 v = *reinterpret_cast<const float4*>(W + (size_t)(k0 + kk) * N_DIM + col0 + c);
            uint4 u = make_uint4(f2tf32(v.x), f2tf32(v.y), f2tf32(v.z), f2tf32(v.w));
            *reinterpret_cast<uint4*>(&Ws[kk * LDW + c]) = u;
        }
        __syncthreads();

        #pragma unroll
        for (int ks = 0; ks < BK; ks += 8) {
            uint32_t afr[2][4];
            #pragma unroll
            for (int mt = 0; mt < 2; mt++) {
                int r = warp_m + mt * 16 + g;
                afr[mt][0] = As[(r    ) * LDA + ks + tg];
                afr[mt][1] = As[(r + 8) * LDA + ks + tg];
                afr[mt][2] = As[(r    ) * LDA + ks + tg + 4];
                afr[mt][3] = As[(r + 8) * LDA + ks + tg + 4];
            }
            uint32_t bfr[8][2];
            #pragma unroll
            for (int nt = 0; nt < 8; nt++) {
                int c = warp_n + nt * 8 + g;
                bfr[nt][0] = Ws[(ks + tg    ) * LDW + c];
                bfr[nt][1] = Ws[(ks + tg + 4) * LDW + c];
            }
            #pragma unroll
            for (int mt = 0; mt < 2; mt++)
                #pragma unroll
                for (int nt = 0; nt < 8; nt++)
                    mma_tf32(acc[mt][nt], afr[mt], bfr[nt]);
        }
        __syncthreads();
    }

    float2 bv[8];
    #pragma unroll
    for (int nt = 0; nt < 8; nt++) {
        if (HAS_BIAS) {
            int c = col0 + warp_n + nt * 8 + tg * 2;
            bv[nt] = *reinterpret_cast<const float2*>(bias + c);
        } else {
            bv[nt] = make_float2(0.f, 0.f);
        }
    }
    #pragma unroll
    for (int mt = 0; mt < 2; mt++) {
        #pragma unroll
        for (int half = 0; half < 2; half++) {
            int m = row0 + warp_m + mt * 16 + half * 8 + g;
            if (m < M) {
                #pragma unroll
                for (int nt = 0; nt < 8; nt++) {
                    int c = col0 + warp_n + nt * 8 + tg * 2;
                    float vx = acc[mt][nt][half * 2 + 0] + bv[nt].x;
                    float vy = acc[mt][nt][half * 2 + 1] + bv[nt].y;
                    if (RELU) { vx = fmaxf(vx, 0.f); vy = fmaxf(vy, 0.f); }
                    if (OUT_BF16) {
                        __nv_bfloat162 p = __floats2bfloat162_rn(vx, vy);
                        *reinterpret_cast<__nv_bfloat162*>(
                            (__nv_bfloat16*)out + (size_t)m * N_DIM + c) = p;
                    } else {
                        *reinterpret_cast<float2*>(
                            (float*)out + (size_t)m * N_DIM + c) = make_float2(vx, vy);
                    }
                }
            }
        }
    }
}

// ---------------------------------------------------------------------------
extern "C" void kernel_launch(void* const* d_in, const int* in_sizes, int n_in,
                              void* d_out, int out_size) {
    const float* x        = (const float*)d_in[0];
    const float* adj_vals = (const float*)d_in[1];
    const int*   adj_row  = (const int*)  d_in[2];
    const int*   adj_col  = (const int*)  d_in[3];
    const float* W1       = (const float*)d_in[4];
    const float* b1       = (const float*)d_in[5];
    const float* W2       = (const float*)d_in[6];
    const float* b2       = (const float*)d_in[7];
    float* y = (float*)d_out;

    float *ax, *h;
    __nv_bfloat16 *xb, *tb;
    int* cnt;
    cudaGetSymbolAddress((void**)&ax,  g_ax);
    cudaGetSymbolAddress((void**)&h,   g_h);
    cudaGetSymbolAddress((void**)&xb,  g_xb);
    cudaGetSymbolAddress((void**)&tb,  g_tb);
    cudaGetSymbolAddress((void**)&cnt, g_cnt);

    // --- CSR build (shared by both SpMMs) ---
    cudaMemsetAsync(cnt, 0, N_NODES * sizeof(int));
    csr_hist_kernel<<<(N_EDGES + 255) / 256, 256>>>(adj_row);
    csr_scan_kernel<<<1, 1024>>>();
    csr_scatter_kernel<<<(N_EDGES + 255) / 256, 256>>>(adj_vals, adj_row, adj_col);

    // --- row sums + bf16 convert: g_inv, g_xb ---
    rowsum_cvt_kernel<<<(N_NODES * 32 + 255) / 256, 256>>>(x);

    // --- spmm1: g_ax = A @ (bf16(x) row-normalized on the fly) ---
    spmm_bf16_kernel<false, true><<<(N_NODES * 32 + 255) / 256, 256>>>(xb, nullptr, ax);

    // --- gemm1: g_h = relu(g_ax @ W1 + b1)  [50000x256], K=128, fp32 out ---
    {
        dim3 grid((N_NODES + 127) / 128, HD / 128);
        gemm_tf32_kernel<HD, XD, true, true, false><<<grid, 256>>>(ax, W1, b1, h, N_NODES);
    }
    // --- gemm2: tb = bf16(g_h @ W2)  [50000x128], K=256 ---
    {
        dim3 grid((N_NODES + 127) / 128, YD / 128);
        gemm_tf32_kernel<YD, HD, false, false, true><<<grid, 256>>>(h, W2, nullptr, tb, N_NODES);
    }
    // --- spmm2: y = b2 + A @ tb ---
    spmm_bf16_kernel<true, false><<<(N_NODES * 32 + 255) / 256, 256>>>(tb, b2, y);
}

// round 11
// speedup vs baseline: 1.0475x; 1.0192x over previous
#include <cuda_runtime.h>
#include <cuda_bf16.h>
#include <cstdint>

#define N_NODES 50000
#define N_EDGES 800000
#define XD 128
#define HD 256
#define YD 128

// Scratch buffers (static device allocations; legal per harness rules)
__device__ __nv_bfloat16 g_xb[(size_t)N_NODES * XD];  // bf16 copy of x
__device__ __nv_bfloat16 g_tb[(size_t)N_NODES * YD];  // bf16 t = h @ W2
__device__ float g_ax [(size_t)N_NODES * XD];          // A @ xn (fp32)
__device__ float g_h  [(size_t)N_NODES * HD];          // relu(ax @ W1 + b1)
__device__ float g_inv[N_NODES];                       // 1/(rowsum(x)+1e-4)

// CSR scratch (rebuilt every launch — deterministic work)
__device__ int  g_cnt   [N_NODES];
__device__ int  g_rowptr[N_NODES + 1];
__device__ int  g_cursor[N_NODES];
__device__ int2 g_edge  [N_EDGES];             // .x = col, .y = val bits

// ---------------------------------------------------------------------------
// CSR build
// ---------------------------------------------------------------------------
__global__ __launch_bounds__(256) void csr_hist_kernel(const int* __restrict__ rows) {
    int e = blockIdx.x * blockDim.x + threadIdx.x;
    if (e < N_EDGES) atomicAdd(&g_cnt[rows[e]], 1);
}

// Two-level shfl scan over 1024 chunk-sums (CHUNK=49 rows each).
__global__ __launch_bounds__(1024) void csr_scan_kernel() {
    __shared__ int warp_tot[32];
    const int t    = threadIdx.x;
    const int lane = t & 31;
    const int wid  = t >> 5;
    const int CHUNK = (N_NODES + 1023) / 1024;   // 49
    const int base = t * CHUNK;

    int local = 0;
    #pragma unroll 7
    for (int i = 0; i < CHUNK; i++) {
        int idx = base + i;
        if (idx < N_NODES) local += g_cnt[idx];
    }
    int v = local;
    #pragma unroll
    for (int o = 1; o < 32; o <<= 1) {
        int u = __shfl_up_sync(0xFFFFFFFFu, v, o);
        if (lane >= o) v += u;
    }
    if (lane == 31) warp_tot[wid] = v;
    __syncthreads();
    if (wid == 0) {
        int w = warp_tot[lane];
        #pragma unroll
        for (int o = 1; o < 32; o <<= 1) {
            int u = __shfl_up_sync(0xFFFFFFFFu, w, o);
            if (lane >= o) w += u;
        }
        warp_tot[lane] = w;
    }
    __syncthreads();
    int incl = v + (wid > 0 ? warp_tot[wid - 1] : 0);
    int pre = incl - local;
    #pragma unroll 7
    for (int i = 0; i < CHUNK; i++) {
        int idx = base + i;
        if (idx < N_NODES) {
            g_rowptr[idx] = pre;
            g_cursor[idx] = pre;
            pre += g_cnt[idx];
        }
    }
    if (t == 1023) g_rowptr[N_NODES] = incl;
}

__global__ __launch_bounds__(256) void csr_scatter_kernel(
    const float* __restrict__ vals,
    const int*   __restrict__ rows,
    const int*   __restrict__ cols)
{
    int e = blockIdx.x * blockDim.x + threadIdx.x;
    if (e >= N_EDGES) return;
    int r = rows[e];
    int c = cols[e];
    float v = vals[e];
    int pos = atomicAdd(&g_cursor[r], 1);
    g_edge[pos] = make_int2(c, __float_as_int(v));
}

// ---------------------------------------------------------------------------
// Fused row-sum + bf16 convert: g_inv[i] = 1/(sum_j x[i,j]+1e-4); g_xb = bf16(x).
// One warp per row.
// ---------------------------------------------------------------------------
__global__ __launch_bounds__(256) void rowsum_cvt_kernel(const float* __restrict__ x) {
    int row  = (blockIdx.x * blockDim.x + threadIdx.x) >> 5;
    int lane = threadIdx.x & 31;
    if (row >= N_NODES) return;
    float4 v = reinterpret_cast<const float4*>(x + (size_t)row * XD)[lane];
    float s = v.x + v.y + v.z + v.w;
    #pragma unroll
    for (int o = 16; o > 0; o >>= 1) s += __shfl_xor_sync(0xFFFFFFFFu, s, o);
    if (lane == 0) g_inv[row] = 1.0f / (s + 1e-4f);
    __nv_bfloat162 p0 = __floats2bfloat162_rn(v.x, v.y);
    __nv_bfloat162 p1 = __floats2bfloat162_rn(v.z, v.w);
    uint2 u = make_uint2(*reinterpret_cast<uint32_t*>(&p0),
                         *reinterpret_cast<uint32_t*>(&p1));
    reinterpret_cast<uint2*>(g_xb)[(size_t)row * 32 + lane] = u;
}

// ---------------------------------------------------------------------------
// CSR SpMM, bf16 source, D=128 — HALF-WARP per row.
// Lanes 0-15 process one row, lanes 16-31 an independent row: every warp-wide
// instruction covers 2 edges, halving the issue count vs warp-per-row, and
// doubling per-warp MLP (gathers are 16B uint4 per lane).
//   dst[row,:] = (bias?) + sum_e val_e * (inv[col_e]?) * bf16src[col_e,:]
// ---------------------------------------------------------------------------
__device__ __forceinline__ void fma_bf16x8(float* acc, uint4 m, float v) {
    float2 f0 = __bfloat1622float2(*reinterpret_cast<__nv_bfloat162*>(&m.x));
    float2 f1 = __bfloat1622float2(*reinterpret_cast<__nv_bfloat162*>(&m.y));
    float2 f2 = __bfloat1622float2(*reinterpret_cast<__nv_bfloat162*>(&m.z));
    float2 f3 = __bfloat1622float2(*reinterpret_cast<__nv_bfloat162*>(&m.w));
    acc[0] = fmaf(v, f0.x, acc[0]); acc[1] = fmaf(v, f0.y, acc[1]);
    acc[2] = fmaf(v, f1.x, acc[2]); acc[3] = fmaf(v, f1.y, acc[3]);
    acc[4] = fmaf(v, f2.x, acc[4]); acc[5] = fmaf(v, f2.y, acc[5]);
    acc[6] = fmaf(v, f3.x, acc[6]); acc[7] = fmaf(v, f3.y, acc[7]);
}

template<bool HAS_BIAS, bool SCALE_SRC>
__global__ __launch_bounds__(256) void spmm_bf16_hw_kernel(
    const __nv_bfloat16* __restrict__ src,
    const float*         __restrict__ bias,
    float*               __restrict__ dst)
{
    int gtid = blockIdx.x * blockDim.x + threadIdx.x;
    int row  = gtid >> 4;                 // half-warp per row
    int lane = threadIdx.x & 15;          // 0..15 within half-warp
    if (row >= N_NODES) return;

    int s = g_rowptr[row];
    int e = g_rowptr[row + 1];

    float acc[8];
    if (HAS_BIAS) {
        float4 b0 = reinterpret_cast<const float4*>(bias)[lane * 2];
        float4 b1 = reinterpret_cast<const float4*>(bias)[lane * 2 + 1];
        acc[0] = b0.x; acc[1] = b0.y; acc[2] = b0.z; acc[3] = b0.w;
        acc[4] = b1.x; acc[5] = b1.y; acc[6] = b1.z; acc[7] = b1.w;
    } else {
        #pragma unroll
        for (int j = 0; j < 8; j++) acc[j] = 0.f;
    }

    const uint4* src4 = reinterpret_cast<const uint4*>(src);  // row = 16 uint4

    int i = s;
    #pragma unroll 1
    for (; i + 4 <= e; i += 4) {
        int2 e0 = __ldg(&g_edge[i]);
        int2 e1 = __ldg(&g_edge[i + 1]);
        int2 e2 = __ldg(&g_edge[i + 2]);
        int2 e3 = __ldg(&g_edge[i + 3]);
        float v0 = __int_as_float(e0.y);
        float v1 = __int_as_float(e1.y);
        float v2 = __int_as_float(e2.y);
        float v3 = __int_as_float(e3.y);
        if (SCALE_SRC) {
            v0 *= __ldg(&g_inv[e0.x]);
            v1 *= __ldg(&g_inv[e1.x]);
            v2 *= __ldg(&g_inv[e2.x]);
            v3 *= __ldg(&g_inv[e3.x]);
        }
        uint4 m0 = __ldg(&src4[(size_t)e0.x * 16 + lane]);
        uint4 m1 = __ldg(&src4[(size_t)e1.x * 16 + lane]);
        uint4 m2 = __ldg(&src4[(size_t)e2.x * 16 + lane]);
        uint4 m3 = __ldg(&src4[(size_t)e3.x * 16 + lane]);
        fma_bf16x8(acc, m0, v0);
        fma_bf16x8(acc, m1, v1);
        fma_bf16x8(acc, m2, v2);
        fma_bf16x8(acc, m3, v3);
    }
    for (; i < e; i++) {
        int2 e0 = __ldg(&g_edge[i]);
        float v0 = __int_as_float(e0.y);
        if (SCALE_SRC) v0 *= __ldg(&g_inv[e0.x]);
        uint4 m0 = __ldg(&src4[(size_t)e0.x * 16 + lane]);
        fma_bf16x8(acc, m0, v0);
    }

    float4* drow = reinterpret_cast<float4*>(dst) + (size_t)row * 32 + lane * 2;
    drow[0] = make_float4(acc[0], acc[1], acc[2], acc[3]);
    drow[1] = make_float4(acc[4], acc[5], acc[6], acc[7]);
}

// ---------------------------------------------------------------------------
// TF32 tensor-core GEMM: out[M,N] = op(A[M,K] @ W[K,N] + bias)
// Block tile 128x128, BK=32, 8 warps, warp tile 32x64. OUT_BF16 stores bf16.
// ---------------------------------------------------------------------------
__device__ __forceinline__ uint32_t f2tf32(float f) {
    uint32_t r;
    asm("cvt.rna.tf32.f32 %0, %1;" : "=r"(r) : "f"(f));
    return r;
}
__device__ __forceinline__ void mma_tf32(float* d, const uint32_t* a, const uint32_t* b) {
    asm volatile("mma.sync.aligned.m16n8k8.row.col.f32.tf32.tf32.f32 "
                 "{%0,%1,%2,%3}, {%4,%5,%6,%7}, {%8,%9}, {%0,%1,%2,%3};"
                 : "+f"(d[0]), "+f"(d[1]), "+f"(d[2]), "+f"(d[3])
                 : "r"(a[0]), "r"(a[1]), "r"(a[2]), "r"(a[3]),
                   "r"(b[0]), "r"(b[1]));
}

template<int N_DIM, int K_DIM, bool RELU, bool HAS_BIAS, bool OUT_BF16>
__global__ __launch_bounds__(256) void gemm_tf32_kernel(
    const float* __restrict__ A,
    const float* __restrict__ W,
    const float* __restrict__ bias,
    void*        __restrict__ out,
    int M)
{
    constexpr int BM = 128, BN = 128, BK = 32;
    constexpr int LDA = BK + 4;   // 36
    constexpr int LDW = BN + 4;   // 132
    __shared__ uint32_t As[BM * LDA];
    __shared__ uint32_t Ws[BK * LDW];

    const int tid  = threadIdx.x;
    const int lane = tid & 31;
    const int wid  = tid >> 5;
    const int g    = lane >> 2;
    const int tg   = lane & 3;
    const int warp_m = (wid & 3) * 32;
    const int warp_n = (wid >> 2) * 64;
    const int row0 = blockIdx.x * BM;
    const int col0 = blockIdx.y * BN;

    float acc[2][8][4];
    #pragma unroll
    for (int mt = 0; mt < 2; mt++)
        #pragma unroll
        for (int nt = 0; nt < 8; nt++)
            #pragma unroll
            for (int j = 0; j < 4; j++) acc[mt][nt][j] = 0.f;

    for (int k0 = 0; k0 < K_DIM; k0 += BK) {
        #pragma unroll
        for (int i = 0; i < 4; i++) {
            int idx = tid + 256 * i;
            int r   = idx >> 3;
            int kc  = (idx & 7) * 4;
            int gr  = row0 + r; if (gr >= M) gr = M - 1;
            float4 v = *reinterpret_cast<const float4*>(A + (size_t)gr * K_DIM + k0 + kc);
            uint4 u = make_uint4(f2tf32(v.x), f2tf32(v.y), f2tf32(v.z), f2tf32(v.w));
            *reinterpret_cast<uint4*>(&As[r * LDA + kc]) = u;
        }
        #pragma unroll
        for (int i = 0; i < 4; i++) {
            int idx = tid + 256 * i;
            int kk  = idx >> 5;
            int c   = (idx & 31) * 4;
            float4 v = *reinterpret_cast<const float4*>(W + (size_t)(k0 + kk) * N_DIM + col0 + c);
            uint4 u = make_uint4(f2tf32(v.x), f2tf32(v.y), f2tf32(v.z), f2tf32(v.w));
            *reinterpret_cast<uint4*>(&Ws[kk * LDW + c]) = u;
        }
        __syncthreads();

        #pragma unroll
        for (int ks = 0; ks < BK; ks += 8) {
            uint32_t afr[2][4];
            #pragma unroll
            for (int mt = 0; mt < 2; mt++) {
                int r = warp_m + mt * 16 + g;
                afr[mt][0] = As[(r    ) * LDA + ks + tg];
                afr[mt][1] = As[(r + 8) * LDA + ks + tg];
                afr[mt][2] = As[(r    ) * LDA + ks + tg + 4];
                afr[mt][3] = As[(r + 8) * LDA + ks + tg + 4];
            }
            uint32_t bfr[8][2];
            #pragma unroll
            for (int nt = 0; nt < 8; nt++) {
                int c = warp_n + nt * 8 + g;
                bfr[nt][0] = Ws[(ks + tg    ) * LDW + c];
                bfr[nt][1] = Ws[(ks + tg + 4) * LDW + c];
            }
            #pragma unroll
            for (int mt = 0; mt < 2; mt++)
                #pragma unroll
                for (int nt = 0; nt < 8; nt++)
                    mma_tf32(acc[mt][nt], afr[mt], bfr[nt]);
        }
        __syncthreads();
    }

    float2 bv[8];
    #pragma unroll
    for (int nt = 0; nt < 8; nt++) {
        if (HAS_BIAS) {
            int c = col0 + warp_n + nt * 8 + tg * 2;
            bv[nt] = *reinterpret_cast<const float2*>(bias + c);
        } else {
            bv[nt] = make_float2(0.f, 0.f);
        }
    }
    #pragma unroll
    for (int mt = 0; mt < 2; mt++) {
        #pragma unroll
        for (int half = 0; half < 2; half++) {
            int m = row0 + warp_m + mt * 16 + half * 8 + g;
            if (m < M) {
                #pragma unroll
                for (int nt = 0; nt < 8; nt++) {
                    int c = col0 + warp_n + nt * 8 + tg * 2;
                    float vx = acc[mt][nt][half * 2 + 0] + bv[nt].x;
                    float vy = acc[mt][nt][half * 2 + 1] + bv[nt].y;
                    if (RELU) { vx = fmaxf(vx, 0.f); vy = fmaxf(vy, 0.f); }
                    if (OUT_BF16) {
                        __nv_bfloat162 p = __floats2bfloat162_rn(vx, vy);
                        *reinterpret_cast<__nv_bfloat162*>(
                            (__nv_bfloat16*)out + (size_t)m * N_DIM + c) = p;
                    } else {
                        *reinterpret_cast<float2*>(
                            (float*)out + (size_t)m * N_DIM + c) = make_float2(vx, vy);
                    }
                }
            }
        }
    }
}

// ---------------------------------------------------------------------------
extern "C" void kernel_launch(void* const* d_in, const int* in_sizes, int n_in,
                              void* d_out, int out_size) {
    const float* x        = (const float*)d_in[0];
    const float* adj_vals = (const float*)d_in[1];
    const int*   adj_row  = (const int*)  d_in[2];
    const int*   adj_col  = (const int*)  d_in[3];
    const float* W1       = (const float*)d_in[4];
    const float* b1       = (const float*)d_in[5];
    const float* W2       = (const float*)d_in[6];
    const float* b2       = (const float*)d_in[7];
    float* y = (float*)d_out;

    float *ax, *h;
    __nv_bfloat16 *xb, *tb;
    int* cnt;
    cudaGetSymbolAddress((void**)&ax,  g_ax);
    cudaGetSymbolAddress((void**)&h,   g_h);
    cudaGetSymbolAddress((void**)&xb,  g_xb);
    cudaGetSymbolAddress((void**)&tb,  g_tb);
    cudaGetSymbolAddress((void**)&cnt, g_cnt);

    // --- CSR build (shared by both SpMMs) ---
    cudaMemsetAsync(cnt, 0, N_NODES * sizeof(int));
    csr_hist_kernel<<<(N_EDGES + 255) / 256, 256>>>(adj_row);
    csr_scan_kernel<<<1, 1024>>>();
    csr_scatter_kernel<<<(N_EDGES + 255) / 256, 256>>>(adj_vals, adj_row, adj_col);

    // --- row sums + bf16 convert: g_inv, g_xb ---
    rowsum_cvt_kernel<<<(N_NODES * 32 + 255) / 256, 256>>>(x);

    // --- spmm1: g_ax = A @ (bf16(x) row-normalized on the fly) ---
    spmm_bf16_hw_kernel<false, true><<<(N_NODES * 16 + 255) / 256, 256>>>(xb, nullptr, ax);

    // --- gemm1: g_h = relu(g_ax @ W1 + b1)  [50000x256], K=128, fp32 out ---
    {
        dim3 grid((N_NODES + 127) / 128, HD / 128);
        gemm_tf32_kernel<HD, XD, true, true, false><<<grid, 256>>>(ax, W1, b1, h, N_NODES);
    }
    // --- gemm2: tb = bf16(g_h @ W2)  [50000x128], K=256 ---
    {
        dim3 grid((N_NODES + 127) / 128, YD / 128);
        gemm_tf32_kernel<YD, HD, false, false, true><<<grid, 256>>>(h, W2, nullptr, tb, N_NODES);
    }
    // --- spmm2: y = b2 + A @ tb ---
    spmm_bf16_hw_kernel<true, false><<<(N_NODES * 16 + 255) / 256, 256>>>(tb, b2, y);
}